// round 1
// baseline (speedup 1.0000x reference)
#include <cuda_runtime.h>
#include <cstdint>

#define T_DIM 8192
#define D_DIM 5120
#define H_DIM 13824

// ---------------- scratch (device globals: allocation-free rule) --------------
__device__ int8_t d_w1s8[(size_t)H_DIM * D_DIM];   // 70.8 MB
__device__ int8_t d_w2s8[(size_t)D_DIM * H_DIM];   // 70.8 MB
__device__ int8_t d_q1[(size_t)T_DIM * D_DIM];     // 41.9 MB
__device__ int8_t d_q2[(size_t)T_DIM * H_DIM];     // 113 MB
__device__ float  d_g [(size_t)T_DIM * H_DIM];     // 453 MB
__device__ float  d_s1[T_DIM];
__device__ int    d_sum1[T_DIM];
__device__ float  d_s2[T_DIM];
__device__ int    d_sum2[T_DIM];

// ---------------- weight convert: int32 code [0,255] -> s8 (w-128) ------------
__global__ void convert_weights(const int* __restrict__ w, int8_t* __restrict__ o, int n4) {
    int i = blockIdx.x * blockDim.x + threadIdx.x;
    if (i < n4) {
        int4 v = ((const int4*)w)[i];
        unsigned p = (unsigned)((v.x - 128) & 0xff)
                   | ((unsigned)((v.y - 128) & 0xff) << 8)
                   | ((unsigned)((v.z - 128) & 0xff) << 16)
                   | ((unsigned)((v.w - 128) & 0xff) << 24);
        ((unsigned*)o)[i] = p;
    }
}

// ---------------- per-row dynamic int8 quant (max / scale / round / sum) ------
template<int THREADS, int V>
__global__ void quant_rows(const float* __restrict__ x, int8_t* __restrict__ q,
                           float* __restrict__ s_out, int* __restrict__ sum_out,
                           int cols) {
    constexpr int NW = THREADS / 32;
    __shared__ float smax[NW];
    __shared__ int   ssum[NW];
    int row  = blockIdx.x;
    int tid  = threadIdx.x;
    int lane = tid & 31, w = tid >> 5;

    const float4* xr = (const float4*)(x + (size_t)row * cols);
    float4 v[V];
    float m = 0.0f;
#pragma unroll
    for (int i = 0; i < V; i++) {
        v[i] = xr[i * THREADS + tid];
        m = fmaxf(m, fmaxf(fmaxf(fabsf(v[i].x), fabsf(v[i].y)),
                           fmaxf(fabsf(v[i].z), fabsf(v[i].w))));
    }
#pragma unroll
    for (int o = 16; o; o >>= 1) m = fmaxf(m, __shfl_xor_sync(0xffffffffu, m, o));
    if (lane == 0) smax[w] = m;
    __syncthreads();
    if (tid == 0) {
        float mm = smax[0];
#pragma unroll
        for (int i = 1; i < NW; i++) mm = fmaxf(mm, smax[i]);
        smax[0] = mm;
    }
    __syncthreads();
    m = smax[0];

    // s = max(|x|)/127, clamped — bitwise-match reference (IEEE division)
    float s = fmaxf(__fdiv_rn(m, 127.0f), 1e-8f);

    unsigned* qo = (unsigned*)(q + (size_t)row * cols);
    int isum = 0;
#pragma unroll
    for (int i = 0; i < V; i++) {
        float fs[4] = {v[i].x, v[i].y, v[i].z, v[i].w};
        int qi[4];
#pragma unroll
        for (int c = 0; c < 4; c++) {
            float r = rintf(__fdiv_rn(fs[c], s));       // round-half-even, like jnp.round
            r = fminf(fmaxf(r, -127.0f), 127.0f);
            qi[c] = (int)r;
            isum += qi[c];
        }
        unsigned p = (unsigned)(qi[0] & 0xff)
                   | ((unsigned)(qi[1] & 0xff) << 8)
                   | ((unsigned)(qi[2] & 0xff) << 16)
                   | ((unsigned)(qi[3] & 0xff) << 24);
        qo[i * THREADS + tid] = p;
    }
#pragma unroll
    for (int o = 16; o; o >>= 1) isum += __shfl_xor_sync(0xffffffffu, isum, o);
    if (lane == 0) ssum[w] = isum;
    __syncthreads();
    if (tid == 0) {
        int t = 0;
#pragma unroll
        for (int i = 0; i < NW; i++) t += ssum[i];
        sum_out[row] = t;
        s_out[row]   = s;
    }
}

// ---------------- int8 GEMM (mma.sync m16n8k32 s8s8s32) + fused epilogue ------
// C[m,n] = epilogue( sum_k A[m,k]*B[n,k] ),  A:[M,K] rm, B:[N,K] rm (both s8)
__device__ __forceinline__ void mma_s8(int* c, const int* a, const int* b) {
    asm volatile(
        "mma.sync.aligned.m16n8k32.row.col.s32.s8.s8.s32 "
        "{%0,%1,%2,%3}, {%4,%5,%6,%7}, {%8,%9}, {%0,%1,%2,%3};\n"
        : "+r"(c[0]), "+r"(c[1]), "+r"(c[2]), "+r"(c[3])
        : "r"(a[0]), "r"(a[1]), "r"(a[2]), "r"(a[3]), "r"(b[0]), "r"(b[1]));
}

#define SP 80   // smem row pitch (bytes): 20 banks -> conflict-free frag loads

template<bool DO_GELU>
__global__ __launch_bounds__(256)
void gemm_s8_kernel(const int8_t* __restrict__ A, const int8_t* __restrict__ B,
                    float* __restrict__ C, int K, int N,
                    const float* __restrict__ sA, const int* __restrict__ sumA,
                    const float* __restrict__ sW, const float* __restrict__ zp,
                    const float* __restrict__ bias) {
    __shared__ int8_t As[2][128 * SP];
    __shared__ int8_t Bs[2][128 * SP];

    int tid  = threadIdx.x;
    int lane = tid & 31, wid = tid >> 5;
    int warpM = wid >> 2, warpN = wid & 3;          // 2 x 4 warps
    int bm = blockIdx.y * 128, bn = blockIdx.x * 128;

    // global->shared loader mapping: 512 int4 per matrix tile, 2 per thread
    int lrow = tid >> 2;                            // 0..63
    int lcol = (tid & 3) * 16;                      // 0,16,32,48
    const int8_t* Ag = A + (size_t)(bm + lrow) * K + lcol;
    const int8_t* Bg = B + (size_t)(bn + lrow) * K + lcol;
    int so0 = lrow * SP + lcol;
    int so1 = (lrow + 64) * SP + lcol;

    int acc[4][4][4];
#pragma unroll
    for (int mi = 0; mi < 4; mi++)
#pragma unroll
        for (int ni = 0; ni < 4; ni++)
#pragma unroll
            for (int c = 0; c < 4; c++) acc[mi][ni][c] = 0;

    int KT = K >> 6;

    // prologue: tile 0
    int4 ar0 = *(const int4*)Ag;
    int4 ar1 = *(const int4*)(Ag + (size_t)64 * K);
    int4 br0 = *(const int4*)Bg;
    int4 br1 = *(const int4*)(Bg + (size_t)64 * K);
    *(int4*)&As[0][so0] = ar0;
    *(int4*)&As[0][so1] = ar1;
    *(int4*)&Bs[0][so0] = br0;
    *(int4*)&Bs[0][so1] = br1;
    __syncthreads();

    int arow = warpM * 64 + (lane >> 2);
    int brow = warpN * 32 + (lane >> 2);
    int koff = (lane & 3) * 4;

    for (int kt = 0; kt < KT; kt++) {
        int cur = kt & 1, nxt = cur ^ 1;
        if (kt + 1 < KT) {
            const int8_t* Ag2 = Ag + (size_t)(kt + 1) * 64;
            const int8_t* Bg2 = Bg + (size_t)(kt + 1) * 64;
            ar0 = *(const int4*)Ag2;
            ar1 = *(const int4*)(Ag2 + (size_t)64 * K);
            br0 = *(const int4*)Bg2;
            br1 = *(const int4*)(Bg2 + (size_t)64 * K);
        }
#pragma unroll
        for (int ks = 0; ks < 2; ks++) {
            int a[4][4], b[4][2];
            int ac = ks * 32 + koff;
#pragma unroll
            for (int mi = 0; mi < 4; mi++) {
                const int8_t* p = &As[cur][(arow + mi * 16) * SP + ac];
                a[mi][0] = *(const int*)p;
                a[mi][1] = *(const int*)(p + 8 * SP);
                a[mi][2] = *(const int*)(p + 16);
                a[mi][3] = *(const int*)(p + 8 * SP + 16);
            }
#pragma unroll
            for (int ni = 0; ni < 4; ni++) {
                const int8_t* p = &Bs[cur][(brow + ni * 8) * SP + ac];
                b[ni][0] = *(const int*)p;
                b[ni][1] = *(const int*)(p + 16);
            }
#pragma unroll
            for (int mi = 0; mi < 4; mi++)
#pragma unroll
                for (int ni = 0; ni < 4; ni++)
                    mma_s8(acc[mi][ni], a[mi], b[ni]);
        }
        if (kt + 1 < KT) {
            *(int4*)&As[nxt][so0] = ar0;
            *(int4*)&As[nxt][so1] = ar1;
            *(int4*)&Bs[nxt][so0] = br0;
            *(int4*)&Bs[nxt][so1] = br1;
        }
        __syncthreads();
    }

    // epilogue: out = sA*sW*( (acc' + 128*sum) - zp*sum ) + bias  [+ exact GELU]
    int g = lane >> 2, tig = lane & 3;
#pragma unroll
    for (int mi = 0; mi < 4; mi++) {
#pragma unroll
        for (int half = 0; half < 2; half++) {
            int r = bm + warpM * 64 + mi * 16 + g + half * 8;
            float sa   = __ldg(&sA[r]);
            int   ism  = __ldg(&sumA[r]);
            float fsum = (float)ism;
            int   corr = ism * 128;
#pragma unroll
            for (int ni = 0; ni < 4; ni++) {
                int c = bn + warpN * 32 + ni * 8 + tig * 2;
                float sw0 = __ldg(&sW[c]),   sw1 = __ldg(&sW[c + 1]);
                float z0  = __ldg(&zp[c]),   z1  = __ldg(&zp[c + 1]);
                float bb0 = __ldg(&bias[c]), bb1 = __ldg(&bias[c + 1]);
                float f0 = (float)(acc[mi][ni][half * 2 + 0] + corr);
                float f1 = (float)(acc[mi][ni][half * 2 + 1] + corr);
                float v0 = (sa * sw0) * (f0 - z0 * fsum) + bb0;
                float v1 = (sa * sw1) * (f1 - z1 * fsum) + bb1;
                if (DO_GELU) {
                    v0 = v0 * (erff(__fdiv_rn(v0, 1.41421356237309515f)) + 1.0f) * 0.5f;
                    v1 = v1 * (erff(__fdiv_rn(v1, 1.41421356237309515f)) + 1.0f) * 0.5f;
                }
                float2 o2 = make_float2(v0, v1);
                *(float2*)&C[(size_t)r * N + c] = o2;
            }
        }
    }
}

// ---------------- launch -------------------------------------------------------
extern "C" void kernel_launch(void* const* d_in, const int* in_sizes, int n_in,
                              void* d_out, int out_size) {
    const float* x    = (const float*)d_in[0];
    const int*   w1q  = (const int*)  d_in[1];
    const float* w1s  = (const float*)d_in[2];
    const float* w1zp = (const float*)d_in[3];
    const float* b1   = (const float*)d_in[4];
    const int*   w2q  = (const int*)  d_in[5];
    const float* w2s  = (const float*)d_in[6];
    const float* w2zp = (const float*)d_in[7];
    const float* b2   = (const float*)d_in[8];
    float* out = (float*)d_out;

    int8_t *w1s8, *w2s8, *q1, *q2;
    float *g, *s1, *s2;
    int *sum1, *sum2;
    cudaGetSymbolAddress((void**)&w1s8, d_w1s8);
    cudaGetSymbolAddress((void**)&w2s8, d_w2s8);
    cudaGetSymbolAddress((void**)&q1,   d_q1);
    cudaGetSymbolAddress((void**)&q2,   d_q2);
    cudaGetSymbolAddress((void**)&g,    d_g);
    cudaGetSymbolAddress((void**)&s1,   d_s1);
    cudaGetSymbolAddress((void**)&s2,   d_s2);
    cudaGetSymbolAddress((void**)&sum1, d_sum1);
    cudaGetSymbolAddress((void**)&sum2, d_sum2);

    const int n4 = (H_DIM * (int)(D_DIM)) / 4;   // 17,694,720 uint packs per weight
    convert_weights<<<(n4 + 255) / 256, 256>>>(w1q, w1s8, n4);
    convert_weights<<<(n4 + 255) / 256, 256>>>(w2q, w2s8, n4);

    // fc1 input quant: D=5120 -> 1280 float4 = 320 thr * 4
    quant_rows<320, 4><<<T_DIM, 320>>>(x, q1, s1, sum1, D_DIM);

    dim3 g1(H_DIM / 128, T_DIM / 128);           // 108 x 64
    gemm_s8_kernel<true><<<g1, 256>>>(q1, w1s8, g, D_DIM, H_DIM,
                                      s1, sum1, w1s, w1zp, b1);

    // fc2 input quant: H=13824 -> 3456 float4 = 384 thr * 9
    quant_rows<384, 9><<<T_DIM, 384>>>(g, q2, s2, sum2, H_DIM);

    dim3 g2(D_DIM / 128, T_DIM / 128);           // 40 x 64
    gemm_s8_kernel<false><<<g2, 256>>>(q2, w2s8, out, H_DIM, D_DIM,
                                       s2, sum2, w2s, w2zp, b2);
}

// round 3
// speedup vs baseline: 1.1170x; 1.1170x over previous
#include <cuda_runtime.h>
#include <cstdint>

#define T_DIM 8192
#define D_DIM 5120
#define H_DIM 13824

// ---------------- scratch (device globals: allocation-free rule) --------------
__device__ uint8_t d_w1u8[(size_t)H_DIM * D_DIM];   // raw u8 weight codes
__device__ uint8_t d_w2u8[(size_t)D_DIM * H_DIM];
__device__ int8_t  d_q1[(size_t)T_DIM * D_DIM];
__device__ int8_t  d_q2[(size_t)T_DIM * H_DIM];
__device__ float   d_g [(size_t)T_DIM * H_DIM];
__device__ float   d_s1[T_DIM];
__device__ int     d_sum1[T_DIM];
__device__ float   d_s2[T_DIM];
__device__ int     d_sum2[T_DIM];

// ---------------- weight pack: int32 code [0,255] -> u8 raw -------------------
__global__ void convert_weights(const int* __restrict__ w, uint8_t* __restrict__ o, int n4) {
    int i = blockIdx.x * blockDim.x + threadIdx.x;
    if (i < n4) {
        int4 v = ((const int4*)w)[i];
        unsigned p = (unsigned)(v.x & 0xff)
                   | ((unsigned)(v.y & 0xff) << 8)
                   | ((unsigned)(v.z & 0xff) << 16)
                   | ((unsigned)(v.w & 0xff) << 24);
        ((unsigned*)o)[i] = p;
    }
}

// ---------------- per-row dynamic int8 quant ----------------------------------
template<int THREADS, int V>
__global__ void quant_rows(const float* __restrict__ x, int8_t* __restrict__ q,
                           float* __restrict__ s_out, int* __restrict__ sum_out,
                           int cols) {
    constexpr int NW = THREADS / 32;
    __shared__ float smax[NW];
    __shared__ int   ssum[NW];
    int row  = blockIdx.x;
    int tid  = threadIdx.x;
    int lane = tid & 31, w = tid >> 5;

    const float4* xr = (const float4*)(x + (size_t)row * cols);
    float4 v[V];
    float m = 0.0f;
#pragma unroll
    for (int i = 0; i < V; i++) {
        v[i] = xr[i * THREADS + tid];
        m = fmaxf(m, fmaxf(fmaxf(fabsf(v[i].x), fabsf(v[i].y)),
                           fmaxf(fabsf(v[i].z), fabsf(v[i].w))));
    }
#pragma unroll
    for (int o = 16; o; o >>= 1) m = fmaxf(m, __shfl_xor_sync(0xffffffffu, m, o));
    if (lane == 0) smax[w] = m;
    __syncthreads();
    if (tid == 0) {
        float mm = smax[0];
#pragma unroll
        for (int i = 1; i < NW; i++) mm = fmaxf(mm, smax[i]);
        smax[0] = mm;
    }
    __syncthreads();
    m = smax[0];

    float s = fmaxf(__fdiv_rn(m, 127.0f), 1e-8f);

    unsigned* qo = (unsigned*)(q + (size_t)row * cols);
    int isum = 0;
#pragma unroll
    for (int i = 0; i < V; i++) {
        float fs[4] = {v[i].x, v[i].y, v[i].z, v[i].w};
        int qi[4];
#pragma unroll
        for (int c = 0; c < 4; c++) {
            float r = rintf(__fdiv_rn(fs[c], s));
            r = fminf(fmaxf(r, -127.0f), 127.0f);
            qi[c] = (int)r;
            isum += qi[c];
        }
        unsigned p = (unsigned)(qi[0] & 0xff)
                   | ((unsigned)(qi[1] & 0xff) << 8)
                   | ((unsigned)(qi[2] & 0xff) << 16)
                   | ((unsigned)(qi[3] & 0xff) << 24);
        qo[i * THREADS + tid] = p;
    }
#pragma unroll
    for (int o = 16; o; o >>= 1) isum += __shfl_xor_sync(0xffffffffu, isum, o);
    if (lane == 0) ssum[w] = isum;
    __syncthreads();
    if (tid == 0) {
        int t = 0;
#pragma unroll
        for (int i = 0; i < NW; i++) t += ssum[i];
        sum_out[row] = t;
        s_out[row]   = s;
    }
}

// ================= hybrid GEMM: tensor pipe (mma) + fma pipe (dp4a) ===========
// C[m,n] = sum_k A[m,k](s8) * B[n,k](u8). Tile 128x128, BK=64.
// Warps 0-7 (mma) -> cols 0..95; warps 8-11 (dp4a) -> cols 96..127.
// Smem tiles pitch 80B with chunk-XOR swizzle: 16B chunk c of row r stored at
// chunk (c ^ ((r>>3)&3)) -> conflict-free for mma frags AND dp4a int4 loads.

__device__ __forceinline__ uint32_t swoff(int row, int chunk) {
    return (uint32_t)(row * 80 + ((chunk ^ ((row >> 3) & 3)) << 4));
}

__device__ __forceinline__ void mma_s8u8(int* c, const int* a, const int* b) {
    asm volatile(
        "mma.sync.aligned.m16n8k32.row.col.s32.s8.u8.s32 "
        "{%0,%1,%2,%3}, {%4,%5,%6,%7}, {%8,%9}, {%0,%1,%2,%3};\n"
        : "+r"(c[0]), "+r"(c[1]), "+r"(c[2]), "+r"(c[3])
        : "r"(a[0]), "r"(a[1]), "r"(a[2]), "r"(a[3]), "r"(b[0]), "r"(b[1]));
}

__device__ __forceinline__ int dp4a_su(int a, int b, int c) {
    int d;
    asm("dp4a.s32.u32 %0, %1, %2, %3;" : "=r"(d) : "r"(a), "r"(b), "r"(c));
    return d;
}

__device__ __forceinline__ float gelu_exact(float v) {
    return v * (erff(__fdiv_rn(v, 1.41421356237309515f)) + 1.0f) * 0.5f;
}

// global source for load index idx (0..511 -> A tile, 512..1023 -> B tile)
__device__ __forceinline__ const int4* gsrc(const int8_t* A, const uint8_t* B,
                                            int idx, int bm, int bn, int K, int kt) {
    if (idx < 512) {
        int row = idx >> 2, c = idx & 3;
        return (const int4*)(A + (size_t)(bm + row) * K + (size_t)kt * 64 + c * 16);
    } else {
        int j = idx - 512, row = j >> 2, c = j & 3;
        return (const int4*)((const int8_t*)B + (size_t)(bn + row) * K + (size_t)kt * 64 + c * 16);
    }
}

__device__ __forceinline__ void sstore(int8_t* As, int8_t* Bs, int idx, int4 v) {
    if (idx < 512) {
        int row = idx >> 2, c = idx & 3;
        *(int4*)(As + swoff(row, c)) = v;
    } else {
        int j = idx - 512, row = j >> 2, c = j & 3;
        *(int4*)(Bs + swoff(row, c)) = v;
    }
}

template<bool DO_GELU>
__global__ __launch_bounds__(384, 1)
void gemm_hybrid(const int8_t* __restrict__ A, const uint8_t* __restrict__ B,
                 float* __restrict__ C, int K, int N,
                 const float* __restrict__ sA, const int* __restrict__ sumA,
                 const float* __restrict__ sW, const float* __restrict__ zp,
                 const float* __restrict__ bias) {
    __shared__ int8_t As[2][128 * 80];
    __shared__ int8_t Bs[2][128 * 80];

    int tid = threadIdx.x;
    int bm = blockIdx.y * 128, bn = blockIdx.x * 128;
    int KT = K >> 6;

    // role precompute
    int lane = tid & 31, wid = tid >> 5;
    int warpM = wid >> 2, warpN = wid & 3;        // tensor role (wid 0-7): 2x4
    int arowL = warpM * 64 + (lane >> 2);
    int browL = warpN * 24 + (lane >> 2);
    int koff  = (lane & 3) * 4;
    int dtid  = tid - 256;                        // dp4a role (wid 8-11)
    int tRow  = dtid >> 3, tCol = dtid & 7;

    int acc[48];                                  // tensor: [4][3][4]; dp4a: [8][4]
#pragma unroll
    for (int i = 0; i < 48; i++) acc[i] = 0;

    // prologue: tile 0
    {
        int4 v0 = *gsrc(A, B, tid,       bm, bn, K, 0);
        int4 v1 = *gsrc(A, B, tid + 384, bm, bn, K, 0);
        sstore(As[0], Bs[0], tid,       v0);
        sstore(As[0], Bs[0], tid + 384, v1);
        if (tid < 256) {
            int4 v2 = *gsrc(A, B, tid + 768, bm, bn, K, 0);
            sstore(As[0], Bs[0], tid + 768, v2);
        }
    }
    __syncthreads();

    for (int kt = 0; kt < KT; kt++) {
        int cur = kt & 1, nxt = cur ^ 1;
        bool pf = (kt + 1) < KT;
        int4 v0, v1, v2;
        if (pf) {
            v0 = *gsrc(A, B, tid,       bm, bn, K, kt + 1);
            v1 = *gsrc(A, B, tid + 384, bm, bn, K, kt + 1);
            if (tid < 256) v2 = *gsrc(A, B, tid + 768, bm, bn, K, kt + 1);
        }

        if (tid < 256) {                          // ---- tensor warps ----
#pragma unroll
            for (int ks = 0; ks < 2; ks++) {
                int a[4][4], b[3][2];
                int c0 = ks * 2, c1 = c0 + 1;
#pragma unroll
                for (int mi = 0; mi < 4; mi++) {
                    int r0 = arowL + mi * 16, r1 = r0 + 8;
                    a[mi][0] = *(const int*)(As[cur] + swoff(r0, c0) + koff);
                    a[mi][1] = *(const int*)(As[cur] + swoff(r1, c0) + koff);
                    a[mi][2] = *(const int*)(As[cur] + swoff(r0, c1) + koff);
                    a[mi][3] = *(const int*)(As[cur] + swoff(r1, c1) + koff);
                }
#pragma unroll
                for (int ni = 0; ni < 3; ni++) {
                    int rb = browL + ni * 8;
                    b[ni][0] = *(const int*)(Bs[cur] + swoff(rb, c0) + koff);
                    b[ni][1] = *(const int*)(Bs[cur] + swoff(rb, c1) + koff);
                }
#pragma unroll
                for (int mi = 0; mi < 4; mi++)
#pragma unroll
                    for (int ni = 0; ni < 3; ni++)
                        mma_s8u8(&acc[(mi * 3 + ni) * 4], a[mi], b[ni]);
            }
        } else {                                  // ---- dp4a warps ----
#pragma unroll
            for (int c = 0; c < 4; c++) {
                int4 a4[8], b4[4];
#pragma unroll
                for (int i = 0; i < 8; i++)
                    a4[i] = *(const int4*)(As[cur] + swoff(tRow * 8 + i, c));
#pragma unroll
                for (int j = 0; j < 4; j++)
                    b4[j] = *(const int4*)(Bs[cur] + swoff(96 + tCol * 4 + j, c));
#pragma unroll
                for (int w = 0; w < 4; w++) {
#pragma unroll
                    for (int i = 0; i < 8; i++) {
                        int av = ((const int*)&a4[i])[w];
#pragma unroll
                        for (int j = 0; j < 4; j++)
                            acc[i * 4 + j] = dp4a_su(av, ((const int*)&b4[j])[w], acc[i * 4 + j]);
                    }
                }
            }
        }

        if (pf) {
            sstore(As[nxt], Bs[nxt], tid,       v0);
            sstore(As[nxt], Bs[nxt], tid + 384, v1);
            if (tid < 256) sstore(As[nxt], Bs[nxt], tid + 768, v2);
        }
        __syncthreads();
    }

    // ---- epilogues: dequant (+GELU) ----
    if (tid < 256) {
#pragma unroll
        for (int mi = 0; mi < 4; mi++) {
#pragma unroll
            for (int half = 0; half < 2; half++) {
                int r = bm + warpM * 64 + mi * 16 + (lane >> 2) + half * 8;
                float sa   = __ldg(&sA[r]);
                float fsum = (float)__ldg(&sumA[r]);
                float* Crow = C + (size_t)r * N;
#pragma unroll
                for (int ni = 0; ni < 3; ni++) {
                    int cc = bn + warpN * 24 + ni * 8 + (lane & 3) * 2;
                    float f0 = (float)acc[(mi * 3 + ni) * 4 + half * 2 + 0];
                    float f1 = (float)acc[(mi * 3 + ni) * 4 + half * 2 + 1];
                    float v0 = (sa * __ldg(&sW[cc]))     * (f0 - __ldg(&zp[cc])     * fsum) + __ldg(&bias[cc]);
                    float v1 = (sa * __ldg(&sW[cc + 1])) * (f1 - __ldg(&zp[cc + 1]) * fsum) + __ldg(&bias[cc + 1]);
                    if (DO_GELU) { v0 = gelu_exact(v0); v1 = gelu_exact(v1); }
                    *(float2*)(Crow + cc) = make_float2(v0, v1);
                }
            }
        }
    } else {
        int cbase = bn + 96 + tCol * 4;
#pragma unroll
        for (int i = 0; i < 8; i++) {
            int r = bm + tRow * 8 + i;
            float sa   = __ldg(&sA[r]);
            float fsum = (float)__ldg(&sumA[r]);
            float4 o;
            float* ov = (float*)&o;
#pragma unroll
            for (int j = 0; j < 4; j++) {
                int cc = cbase + j;
                float f = (float)acc[i * 4 + j];
                float v = (sa * __ldg(&sW[cc])) * (f - __ldg(&zp[cc]) * fsum) + __ldg(&bias[cc]);
                if (DO_GELU) v = gelu_exact(v);
                ov[j] = v;
            }
            *(float4*)(C + (size_t)r * N + cbase) = o;
        }
    }
}

// ---------------- launch -------------------------------------------------------
extern "C" void kernel_launch(void* const* d_in, const int* in_sizes, int n_in,
                              void* d_out, int out_size) {
    const float* x    = (const float*)d_in[0];
    const int*   w1q  = (const int*)  d_in[1];
    const float* w1s  = (const float*)d_in[2];
    const float* w1zp = (const float*)d_in[3];
    const float* b1   = (const float*)d_in[4];
    const int*   w2q  = (const int*)  d_in[5];
    const float* w2s  = (const float*)d_in[6];
    const float* w2zp = (const float*)d_in[7];
    const float* b2   = (const float*)d_in[8];
    float* out = (float*)d_out;

    uint8_t *w1u8, *w2u8;
    int8_t *q1, *q2;
    float *g, *s1, *s2;
    int *sum1, *sum2;
    cudaGetSymbolAddress((void**)&w1u8, d_w1u8);
    cudaGetSymbolAddress((void**)&w2u8, d_w2u8);
    cudaGetSymbolAddress((void**)&q1,   d_q1);
    cudaGetSymbolAddress((void**)&q2,   d_q2);
    cudaGetSymbolAddress((void**)&g,    d_g);
    cudaGetSymbolAddress((void**)&s1,   d_s1);
    cudaGetSymbolAddress((void**)&s2,   d_s2);
    cudaGetSymbolAddress((void**)&sum1, d_sum1);
    cudaGetSymbolAddress((void**)&sum2, d_sum2);

    const int n4 = (int)(((size_t)H_DIM * D_DIM) / 4);
    convert_weights<<<(n4 + 255) / 256, 256>>>(w1q, w1u8, n4);
    convert_weights<<<(n4 + 255) / 256, 256>>>(w2q, w2u8, n4);

    quant_rows<320, 4><<<T_DIM, 320>>>(x, q1, s1, sum1, D_DIM);

    dim3 g1(H_DIM / 128, T_DIM / 128);   // 108 x 64
    gemm_hybrid<true><<<g1, 384>>>(q1, w1u8, g, D_DIM, H_DIM,
                                   s1, sum1, w1s, w1zp, b1);

    quant_rows<384, 9><<<T_DIM, 384>>>(g, q2, s2, sum2, H_DIM);

    dim3 g2(D_DIM / 128, T_DIM / 128);   // 40 x 64
    gemm_hybrid<false><<<g2, 384>>>(q2, w2u8, out, H_DIM, D_DIM,
                                    s2, sum2, w2s, w2zp, b2);
}

// round 4
// speedup vs baseline: 1.1884x; 1.0639x over previous
#include <cuda_runtime.h>
#include <cstdint>

#define T_DIM 8192
#define D_DIM 5120
#define H_DIM 13824

#define BM 128
#define BN 192        // 96 tensor cols + 96 dp4a cols
#define BK 64
#define PITCH 80
#define A_BYTES (128 * PITCH)          // 10240
#define B_BYTES (192 * PITCH)          // 15360
#define STAGE_BYTES (A_BYTES + B_BYTES) // 25600
#define SMEM_BYTES (2 * STAGE_BYTES)    // 51200

// ---------------- scratch (device globals: allocation-free rule) --------------
__device__ uint8_t d_w1u8[(size_t)H_DIM * D_DIM];
__device__ uint8_t d_w2u8[(size_t)D_DIM * H_DIM];
__device__ int8_t  d_q1[(size_t)T_DIM * D_DIM];
__device__ int8_t  d_q2[(size_t)T_DIM * H_DIM];
__device__ float   d_g [(size_t)T_DIM * H_DIM];
__device__ float   d_s1[T_DIM];
__device__ int     d_sum1[T_DIM];
__device__ float   d_s2[T_DIM];
__device__ int     d_sum2[T_DIM];

// ---------------- weight pack: int32 code [0,255] -> u8 raw -------------------
__global__ void convert_weights(const int* __restrict__ w, uint8_t* __restrict__ o, int n4) {
    int i = blockIdx.x * blockDim.x + threadIdx.x;
    if (i < n4) {
        int4 v = ((const int4*)w)[i];
        unsigned p = (unsigned)(v.x & 0xff)
                   | ((unsigned)(v.y & 0xff) << 8)
                   | ((unsigned)(v.z & 0xff) << 16)
                   | ((unsigned)(v.w & 0xff) << 24);
        ((unsigned*)o)[i] = p;
    }
}

// ---------------- per-row dynamic int8 quant ----------------------------------
template<int THREADS, int V>
__global__ void quant_rows(const float* __restrict__ x, int8_t* __restrict__ q,
                           float* __restrict__ s_out, int* __restrict__ sum_out,
                           int cols) {
    constexpr int NW = THREADS / 32;
    __shared__ float smax[NW];
    __shared__ int   ssum[NW];
    int row  = blockIdx.x;
    int tid  = threadIdx.x;
    int lane = tid & 31, w = tid >> 5;

    const float4* xr = (const float4*)(x + (size_t)row * cols);
    float4 v[V];
    float m = 0.0f;
#pragma unroll
    for (int i = 0; i < V; i++) {
        v[i] = xr[i * THREADS + tid];
        m = fmaxf(m, fmaxf(fmaxf(fabsf(v[i].x), fabsf(v[i].y)),
                           fmaxf(fabsf(v[i].z), fabsf(v[i].w))));
    }
#pragma unroll
    for (int o = 16; o; o >>= 1) m = fmaxf(m, __shfl_xor_sync(0xffffffffu, m, o));
    if (lane == 0) smax[w] = m;
    __syncthreads();
    if (tid == 0) {
        float mm = smax[0];
#pragma unroll
        for (int i = 1; i < NW; i++) mm = fmaxf(mm, smax[i]);
        smax[0] = mm;
    }
    __syncthreads();
    m = smax[0];

    float s = fmaxf(__fdiv_rn(m, 127.0f), 1e-8f);

    unsigned* qo = (unsigned*)(q + (size_t)row * cols);
    int isum = 0;
#pragma unroll
    for (int i = 0; i < V; i++) {
        float fs[4] = {v[i].x, v[i].y, v[i].z, v[i].w};
        int qi[4];
#pragma unroll
        for (int c = 0; c < 4; c++) {
            float r = rintf(__fdiv_rn(fs[c], s));
            r = fminf(fmaxf(r, -127.0f), 127.0f);
            qi[c] = (int)r;
            isum += qi[c];
        }
        unsigned p = (unsigned)(qi[0] & 0xff)
                   | ((unsigned)(qi[1] & 0xff) << 8)
                   | ((unsigned)(qi[2] & 0xff) << 16)
                   | ((unsigned)(qi[3] & 0xff) << 24);
        qo[i * THREADS + tid] = p;
    }
#pragma unroll
    for (int o = 16; o; o >>= 1) isum += __shfl_xor_sync(0xffffffffu, isum, o);
    if (lane == 0) ssum[w] = isum;
    __syncthreads();
    if (tid == 0) {
        int t = 0;
#pragma unroll
        for (int i = 0; i < NW; i++) t += ssum[i];
        sum_out[row] = t;
        s_out[row]   = s;
    }
}

// ================= hybrid GEMM: tensor (96 cols) + dp4a (96 cols) ============
__device__ __forceinline__ uint32_t swoff(int row, int chunk) {
    return (uint32_t)(row * PITCH + ((chunk ^ ((row >> 3) & 3)) << 4));
}

__device__ __forceinline__ void mma_s8u8(int* c, const int* a, const int* b) {
    asm volatile(
        "mma.sync.aligned.m16n8k32.row.col.s32.s8.u8.s32 "
        "{%0,%1,%2,%3}, {%4,%5,%6,%7}, {%8,%9}, {%0,%1,%2,%3};\n"
        : "+r"(c[0]), "+r"(c[1]), "+r"(c[2]), "+r"(c[3])
        : "r"(a[0]), "r"(a[1]), "r"(a[2]), "r"(a[3]), "r"(b[0]), "r"(b[1]));
}

__device__ __forceinline__ int dp4a_su(int a, int b, int c) {
    int d;
    asm("dp4a.s32.u32 %0, %1, %2, %3;" : "=r"(d) : "r"(a), "r"(b), "r"(c));
    return d;
}

__device__ __forceinline__ float gelu_exact(float v) {
    return v * (erff(__fdiv_rn(v, 1.41421356237309515f)) + 1.0f) * 0.5f;
}

__device__ __forceinline__ void cp16(uint32_t dst, const void* src) {
    asm volatile("cp.async.cg.shared.global [%0], [%1], 16;\n" :: "r"(dst), "l"(src));
}
#define CP_COMMIT() asm volatile("cp.async.commit_group;\n" ::: "memory")
#define CP_WAIT0()  asm volatile("cp.async.wait_group 0;\n" ::: "memory")

// issue this thread's cp.async for stage buffer at smem addr `sbase`, k-tile kt
__device__ __forceinline__ void load_stage(uint32_t sbase, const int8_t* A,
                                           const uint8_t* B, int bm, int bn,
                                           int K, int Nn, int kt, int tid) {
    int k0 = kt * BK;
    uint32_t sA = sbase, sB = sbase + A_BYTES;
    {   // A: 512 chunks, one per thread
        int row = tid >> 2, c = tid & 3;
        cp16(sA + swoff(row, c), A + (size_t)(bm + row) * K + k0 + c * 16);
    }
    {   // B: chunks 0..511
        int row = tid >> 2, c = tid & 3;
        int gr = min(bn + row, Nn - 1);
        cp16(sB + swoff(row, c), B + (size_t)gr * K + k0 + c * 16);
    }
    if (tid < 256) {  // B: chunks 512..767 (rows 128..191)
        int idx = tid + 512;
        int row = idx >> 2, c = idx & 3;
        int gr = min(bn + row, Nn - 1);
        cp16(sB + swoff(row, c), B + (size_t)gr * K + k0 + c * 16);
    }
}

template<bool DO_GELU>
__global__ __launch_bounds__(512, 1)
void gemm_hybrid(const int8_t* __restrict__ A, const uint8_t* __restrict__ B,
                 float* __restrict__ C, int K, int N,
                 const float* __restrict__ sA, const int* __restrict__ sumA,
                 const float* __restrict__ sW, const float* __restrict__ zp,
                 const float* __restrict__ bias) {
    extern __shared__ int8_t smem[];
    uint32_t smem_u32;
    asm("{ .reg .u64 t; cvta.to.shared.u64 t, %1; cvt.u32.u64 %0, t; }"
        : "=r"(smem_u32) : "l"(smem));

    int tid = threadIdx.x;
    int bm = blockIdx.y * BM, bn = blockIdx.x * BN;
    int KT = K >> 6;

    int lane = tid & 31, wid = tid >> 5;
    // tensor role (wid 0-7): 2 warpM x 4 warpN, 96 cols
    int warpM = wid >> 2, warpN = wid & 3;
    int arowL = warpM * 64 + (lane >> 2);
    int browL = warpN * 24 + (lane >> 2);
    int koff  = (lane & 3) * 4;
    // dp4a role (wid 8-15): 256 threads, rows 8*tRow..+8, cols 6*tCol..+6
    int dtid = tid - 256;
    int tRow = dtid >> 4, tCol = dtid & 15;

    int acc[48];
#pragma unroll
    for (int i = 0; i < 48; i++) acc[i] = 0;

    // prologue
    load_stage(smem_u32, A, B, bm, bn, K, N, 0, tid);
    CP_COMMIT();
    CP_WAIT0();
    __syncthreads();

    for (int kt = 0; kt < KT; kt++) {
        int cur = kt & 1;
        bool pf = (kt + 1) < KT;
        if (pf) {
            load_stage(smem_u32 + (cur ^ 1) * STAGE_BYTES, A, B, bm, bn, K, N, kt + 1, tid);
            CP_COMMIT();
        }
        const int8_t* Asb = smem + cur * STAGE_BYTES;
        const int8_t* Bsb = Asb + A_BYTES;

        if (tid < 256) {                          // ---- tensor warps ----
#pragma unroll
            for (int ks = 0; ks < 2; ks++) {
                int a[4][4], b[3][2];
                int c0 = ks * 2, c1 = c0 + 1;
#pragma unroll
                for (int mi = 0; mi < 4; mi++) {
                    int r0 = arowL + mi * 16, r1 = r0 + 8;
                    a[mi][0] = *(const int*)(Asb + swoff(r0, c0) + koff);
                    a[mi][1] = *(const int*)(Asb + swoff(r1, c0) + koff);
                    a[mi][2] = *(const int*)(Asb + swoff(r0, c1) + koff);
                    a[mi][3] = *(const int*)(Asb + swoff(r1, c1) + koff);
                }
#pragma unroll
                for (int ni = 0; ni < 3; ni++) {
                    int rb = browL + ni * 8;
                    b[ni][0] = *(const int*)(Bsb + swoff(rb, c0) + koff);
                    b[ni][1] = *(const int*)(Bsb + swoff(rb, c1) + koff);
                }
#pragma unroll
                for (int mi = 0; mi < 4; mi++)
#pragma unroll
                    for (int ni = 0; ni < 3; ni++)
                        mma_s8u8(&acc[(mi * 3 + ni) * 4], a[mi], b[ni]);
            }
        } else {                                  // ---- dp4a warps ----
#pragma unroll
            for (int cc = 0; cc < 4; cc++) {
                int c = (cc + tCol) & 3;          // chunk rotation (bank spread)
                int4 a4[8];
#pragma unroll
                for (int i = 0; i < 8; i++)
                    a4[i] = *(const int4*)(Asb + swoff(tRow * 8 + i, c));
#pragma unroll
                for (int j = 0; j < 6; j++) {
                    int4 b4 = *(const int4*)(Bsb + swoff(96 + tCol * 6 + j, c));
                    const int* bw = (const int*)&b4;
#pragma unroll
                    for (int w = 0; w < 4; w++) {
#pragma unroll
                        for (int i = 0; i < 8; i++)
                            acc[i * 6 + j] = dp4a_su(((const int*)&a4[i])[w], bw[w], acc[i * 6 + j]);
                    }
                }
            }
        }

        if (pf) CP_WAIT0();
        __syncthreads();
    }

    // ---- epilogues: dequant (+GELU) ----
    if (tid < 256) {                              // tensor cols 0..95
#pragma unroll
        for (int mi = 0; mi < 4; mi++) {
#pragma unroll
            for (int half = 0; half < 2; half++) {
                int r = bm + warpM * 64 + mi * 16 + (lane >> 2) + half * 8;
                float sa   = __ldg(&sA[r]);
                float fsum = (float)__ldg(&sumA[r]);
                float* Crow = C + (size_t)r * N;
#pragma unroll
                for (int ni = 0; ni < 3; ni++) {
                    int cc = bn + warpN * 24 + ni * 8 + (lane & 3) * 2;
                    float f0 = (float)acc[(mi * 3 + ni) * 4 + half * 2 + 0];
                    float f1 = (float)acc[(mi * 3 + ni) * 4 + half * 2 + 1];
                    float v0 = (sa * __ldg(&sW[cc]))     * (f0 - __ldg(&zp[cc])     * fsum) + __ldg(&bias[cc]);
                    float v1 = (sa * __ldg(&sW[cc + 1])) * (f1 - __ldg(&zp[cc + 1]) * fsum) + __ldg(&bias[cc + 1]);
                    if (DO_GELU) { v0 = gelu_exact(v0); v1 = gelu_exact(v1); }
                    *(float2*)(Crow + cc) = make_float2(v0, v1);
                }
            }
        }
    } else {                                      // dp4a cols 96..191
        int cbase = bn + 96 + tCol * 6;
#pragma unroll
        for (int i = 0; i < 8; i++) {
            int r = bm + tRow * 8 + i;
            float sa   = __ldg(&sA[r]);
            float fsum = (float)__ldg(&sumA[r]);
            float* Crow = C + (size_t)r * N;
#pragma unroll
            for (int j = 0; j < 6; j++) {
                int cc = cbase + j;
                if (cc < N) {
                    float f = (float)acc[i * 6 + j];
                    float v = (sa * __ldg(&sW[cc])) * (f - __ldg(&zp[cc]) * fsum) + __ldg(&bias[cc]);
                    if (DO_GELU) v = gelu_exact(v);
                    Crow[cc] = v;
                }
            }
        }
    }
}

// ---------------- launch -------------------------------------------------------
extern "C" void kernel_launch(void* const* d_in, const int* in_sizes, int n_in,
                              void* d_out, int out_size) {
    const float* x    = (const float*)d_in[0];
    const int*   w1q  = (const int*)  d_in[1];
    const float* w1s  = (const float*)d_in[2];
    const float* w1zp = (const float*)d_in[3];
    const float* b1   = (const float*)d_in[4];
    const int*   w2q  = (const int*)  d_in[5];
    const float* w2s  = (const float*)d_in[6];
    const float* w2zp = (const float*)d_in[7];
    const float* b2   = (const float*)d_in[8];
    float* out = (float*)d_out;

    uint8_t *w1u8, *w2u8;
    int8_t *q1, *q2;
    float *g, *s1, *s2;
    int *sum1, *sum2;
    cudaGetSymbolAddress((void**)&w1u8, d_w1u8);
    cudaGetSymbolAddress((void**)&w2u8, d_w2u8);
    cudaGetSymbolAddress((void**)&q1,   d_q1);
    cudaGetSymbolAddress((void**)&q2,   d_q2);
    cudaGetSymbolAddress((void**)&g,    d_g);
    cudaGetSymbolAddress((void**)&s1,   d_s1);
    cudaGetSymbolAddress((void**)&s2,   d_s2);
    cudaGetSymbolAddress((void**)&sum1, d_sum1);
    cudaGetSymbolAddress((void**)&sum2, d_sum2);

    cudaFuncSetAttribute(gemm_hybrid<true>,
                         cudaFuncAttributeMaxDynamicSharedMemorySize, SMEM_BYTES);
    cudaFuncSetAttribute(gemm_hybrid<false>,
                         cudaFuncAttributeMaxDynamicSharedMemorySize, SMEM_BYTES);

    const int n4 = (int)(((size_t)H_DIM * D_DIM) / 4);
    convert_weights<<<(n4 + 255) / 256, 256>>>(w1q, w1u8, n4);
    convert_weights<<<(n4 + 255) / 256, 256>>>(w2q, w2u8, n4);

    quant_rows<320, 4><<<T_DIM, 320>>>(x, q1, s1, sum1, D_DIM);

    dim3 g1(H_DIM / BN, T_DIM / BM);             // 72 x 64
    gemm_hybrid<true><<<g1, 512, SMEM_BYTES>>>(q1, w1u8, g, D_DIM, H_DIM,
                                               s1, sum1, w1s, w1zp, b1);

    quant_rows<384, 9><<<T_DIM, 384>>>(g, q2, s2, sum2, H_DIM);

    dim3 g2((D_DIM + BN - 1) / BN, T_DIM / BM);  // 27 x 64
    gemm_hybrid<false><<<g2, 512, SMEM_BYTES>>>(q2, w2u8, out, H_DIM, D_DIM,
                                                s2, sum2, w2s, w2zp, b2);
}